// round 10
// baseline (speedup 1.0000x reference)
#include <cuda_runtime.h>
#include <math.h>

typedef unsigned long long u64;

#define ZSPLIT 2

// Partial planes + per-tile arrival counters (zero-initialized; finisher
// resets its counter so graph replays start clean). No allocation allowed.
__device__ float g_part[ZSPLIT][128 * 512];
__device__ unsigned int g_cnt[1024];

__device__ __forceinline__ void upk2(u64 v, float& lo, float& hi) {
    asm("mov.b64 {%0, %1}, %2;" : "=f"(lo), "=f"(hi) : "l"(v));
}
__device__ __forceinline__ u64 pk2(float lo, float hi) {
    u64 r; asm("mov.b64 %0, {%1, %2};" : "=l"(r) : "f"(lo), "f"(hi)); return r;
}
__device__ __forceinline__ u64 fma2(u64 a, u64 b, u64 c) {
    u64 d; asm("fma.rn.f32x2 %0, %1, %2, %3;" : "=l"(d) : "l"(a), "l"(b), "l"(c)); return d;
}
__device__ __forceinline__ u64 add2(u64 a, u64 b) {
    u64 d; asm("add.rn.f32x2 %0, %1, %2;" : "=l"(d) : "l"(a), "l"(b)); return d;
}
__device__ __forceinline__ float ex2f(float x) {
    float e; asm("ex2.approx.ftz.f32 %0, %1;" : "=f"(e) : "f"(x)); return e;
}

#define MAGIC_F 12582912.0f   // 1.5 * 2^23

// Hybrid MUFU/poly mainloop (identical to the R8 best); ADD_AM2 = slow path.
template <bool ADD_AM2>
__device__ __forceinline__ float kde_loop(
    const ulonglong2* __restrict__ hx,
    const ulonglong2* __restrict__ hy,
    const ulonglong2* __restrict__ hs,
    u64 qx2, u64 qy2, u64 am22, int nq)
{
    const u64 C0 = pk2(1.0f, 1.0f);
    const u64 C1 = pk2(0.69314718056f, 0.69314718056f);
    const u64 C2 = pk2(0.24022650696f, 0.24022650696f);
    const u64 C3 = pk2(0.05550410866f, 0.05550410866f);
    const u64 C4 = pk2(0.00961812911f, 0.00961812911f);
    const u64 C5 = pk2(0.00133335581f, 0.00133335581f);
    const u64 MG   = pk2(MAGIC_F, MAGIC_F);
    const u64 NMG  = pk2(-MAGIC_F, -MAGIC_F);
    const u64 NONE = pk2(-1.0f, -1.0f);

    float sA = 0.f, sB = 0.f, sC = 0.f, sD = 0.f, sE = 0.f, sF = 0.f;
    u64 accP = 0ull;

    #pragma unroll 4
    for (int q = 0; q < nq; q++) {
        int j = 2 * q;
        ulonglong2 X0 = hx[j], X1 = hx[j + 1];
        ulonglong2 Y0 = hy[j], Y1 = hy[j + 1];
        ulonglong2 S0 = hs[j], S1 = hs[j + 1];

        // dot products: 2 packed fma per pair (3rd add only on slow path)
        u64 ta = fma2(qx2, X0.x, S0.x); ta = fma2(qy2, Y0.x, ta);
        u64 tb = fma2(qx2, X0.y, S0.y); tb = fma2(qy2, Y0.y, tb);
        u64 tc = fma2(qx2, X1.x, S1.x); tc = fma2(qy2, Y1.x, tc);
        u64 td = fma2(qx2, X1.y, S1.y); td = fma2(qy2, Y1.y, td);
        if (ADD_AM2) {
            ta = add2(ta, am22);
            tb = add2(tb, am22);
            tc = add2(tc, am22);
            td = add2(td, am22);
        }

        // 3 pairs via MUFU ex2, scalar-FADD accumulate
        float a0, a1, b0, b1, c0, c1;
        upk2(ta, a0, a1);
        upk2(tb, b0, b1);
        upk2(tc, c0, c1);
        sA += ex2f(a0);
        sB += ex2f(a1);
        sC += ex2f(b0);
        sD += ex2f(b1);
        sE += ex2f(c0);
        sF += ex2f(c1);

        // 1 pair via packed polynomial exp2 (FMA + ALU pipes)
        float d0, d1;
        upk2(td, d0, d1);
        d0 = fmaxf(d0, -125.0f);        // underflow clamp
        d1 = fmaxf(d1, -125.0f);
        u64 tdc = pk2(d0, d1);
        u64 k2 = add2(tdc, MG);         // round-to-nearest in mantissa
        u64 n2 = add2(k2, NMG);         // n = rint(t)
        u64 f2 = fma2(NONE, n2, tdc);   // f = t - n in [-0.5, 0.5]
        u64 p2 = fma2(C5, f2, C4);
        p2 = fma2(p2, f2, C3);
        p2 = fma2(p2, f2, C2);
        p2 = fma2(p2, f2, C1);
        p2 = fma2(p2, f2, C0);
        float kf0, kf1;
        upk2(k2, kf0, kf1);
        int s0b = (__float_as_int(kf0) << 23) + 0x3F800000;  // 2^n bits
        int s1b = (__float_as_int(kf1) << 23) + 0x3F800000;
        u64 s2 = pk2(__int_as_float(s0b), __int_as_float(s1b));
        accP = fma2(p2, s2, accP);
    }

    float p0, p1;
    upk2(accP, p0, p1);
    return ((sA + sB) + (sC + sD)) + ((sE + sF) + (p0 + p1));
}

// grid = (M/64, B, ZSPLIT), 64 threads. Each block handles N/ZSPLIT samples,
// stores its partial plane; the LAST of the two sibling blocks fuses the
// reduction (fixed order plane0+plane1) and resets the tile counter.
__global__ __launch_bounds__(64)
void kde_main_kernel(const float* __restrict__ inputs,
                     const float* __restrict__ pts,
                     float* __restrict__ out,
                     int N, int M, float gamma2, float scale_out) {
    const int b = blockIdx.y;
    const int z = blockIdx.z;
    const int m = blockIdx.x * 64 + threadIdx.x;
    const int Nc = N / ZSPLIT;

    __shared__ __align__(16) float sxx[2048 / ZSPLIT];
    __shared__ __align__(16) float sxy[2048 / ZSPLIT];
    __shared__ __align__(16) float ssn[2048 / ZSPLIT];

    // Stage + preprocess this block's chunk: (Nc,2) -> SoA (xx, xy, -g2*|x|^2)
    {
        const float4* src = (const float4*)(inputs + (size_t)b * N * 2
                                                   + (size_t)z * Nc * 2);
        const int nv = Nc >> 1;          // float4s, 2 samples each
        for (int j = threadIdx.x; j < nv; j += 64) {
            float4 v = src[j];
            int n0 = 2 * j;
            sxx[n0]     = v.x;  sxy[n0]     = v.y;
            ssn[n0]     = -gamma2 * fmaf(v.x, v.x, v.y * v.y);
            sxx[n0 + 1] = v.z;  sxy[n0 + 1] = v.w;
            ssn[n0 + 1] = -gamma2 * fmaf(v.z, v.z, v.w * v.w);
        }
    }

    // Point constants (log2 units): arg = am2 + qx*xx + qy*xy + sn
    const float px = pts[2 * m], py = pts[2 * m + 1];
    const float qxs = 2.0f * gamma2 * px;
    const float qys = 2.0f * gamma2 * py;
    const float am2s = -gamma2 * fmaf(px, px, py * py);

    __syncthreads();

    const u64 qx2  = pk2(qxs, qxs);
    const u64 qy2  = pk2(qys, qys);
    const u64 am22 = pk2(am2s, am2s);

    const ulonglong2* hx = (const ulonglong2*)sxx;
    const ulonglong2* hy = (const ulonglong2*)sxy;
    const ulonglong2* hs = (const ulonglong2*)ssn;
    const int nq = Nc >> 3;

    // Fast path factors exp2(am2) out of the loop (safe for am2 >= -100).
    const bool fast = __all_sync(0xffffffffu, am2s >= -100.0f);

    float total, fin_scale;
    if (fast) {
        total = kde_loop<false>(hx, hy, hs, qx2, qy2, am22, nq);
        fin_scale = scale_out * ex2f(am2s);
    } else {
        total = kde_loop<true>(hx, hy, hs, qx2, qy2, am22, nq);
        fin_scale = scale_out;
    }
    total *= fin_scale;

    // Publish partial, then the second-arriving sibling block reduces.
    const size_t bm = (size_t)b * M + m;
    g_part[z][bm] = total;
    __threadfence();

    const int tile = b * gridDim.x + blockIdx.x;
    __shared__ unsigned int s_old;
    if (threadIdx.x == 0) s_old = atomicAdd(&g_cnt[tile], 1u);
    __syncthreads();

    if (s_old == ZSPLIT - 1) {          // we arrived last: partials visible
        __threadfence();                // order our loads after the atomic
        float p0 = (z == 0) ? total : g_part[0][bm];
        float p1 = (z == 1) ? total : g_part[1][bm];
        out[bm] = p0 + p1;              // fixed order: plane0 + plane1
        if (threadIdx.x == 0) g_cnt[tile] = 0;   // reset for next replay
    }
}

extern "C" void kernel_launch(void* const* d_in, const int* in_sizes, int n_in,
                              void* d_out, int out_size) {
    const float* inputs = (const float*)d_in[0];   // (B, N, 2) float32
    const float* pts    = (const float*)d_in[1];   // (M, 2) float32
    float* out          = (float*)d_out;           // (B, M) float32

    const int d = 2;
    const int M  = in_sizes[1] / d;                // 512
    const int BN = in_sizes[0] / d;                // B*N
    const int B  = out_size / M;                   // 128
    const int N  = BN / B;                         // 2048

    // Silverman bandwidth (d=2)
    double h = pow(4.0 / (d + 2), 1.0 / (d + 4)) * pow((double)N, -1.0 / (d + 4));
    double coef = 1.0 / pow(2.0 * M_PI * h * h, d / 2.0);
    double gamma = 0.5 / (h * h);
    float gamma2 = (float)(gamma * 1.4426950408889634);  // fold 1/ln2 for ex2
    float scale_out = (float)(coef / (double)N);

    dim3 grid(M / 64, B, ZSPLIT);   // (8, 128, 2) = 2048 blocks, 64 threads
    kde_main_kernel<<<grid, 64>>>(inputs, pts, out, N, M, gamma2, scale_out);
}

// round 12
// speedup vs baseline: 1.1857x; 1.1857x over previous
#include <cuda_runtime.h>
#include <math.h>

typedef unsigned long long u64;

__device__ __forceinline__ void upk2(u64 v, float& lo, float& hi) {
    asm("mov.b64 {%0, %1}, %2;" : "=f"(lo), "=f"(hi) : "l"(v));
}
__device__ __forceinline__ u64 pk2(float lo, float hi) {
    u64 r; asm("mov.b64 %0, {%1, %2};" : "=l"(r) : "f"(lo), "f"(hi)); return r;
}
__device__ __forceinline__ u64 fma2(u64 a, u64 b, u64 c) {
    u64 d; asm("fma.rn.f32x2 %0, %1, %2, %3;" : "=l"(d) : "l"(a), "l"(b), "l"(c)); return d;
}
__device__ __forceinline__ u64 add2(u64 a, u64 b) {
    u64 d; asm("add.rn.f32x2 %0, %1, %2;" : "=l"(d) : "l"(a), "l"(b)); return d;
}
// pack a fp32 pair (as u64) into f16x2 with round-to-nearest
__device__ __forceinline__ unsigned int f16x2_of(u64 t) {
    float lo, hi; upk2(t, lo, hi);
    unsigned int r;
    asm("cvt.rn.f16x2.f32 %0, %1, %2;" : "=r"(r) : "f"(hi), "f"(lo));
    return r;
}
// packed fp16 exp2: ONE MUFU instruction, TWO exponentials
__device__ __forceinline__ unsigned int hex2(unsigned int x) {
    unsigned int r; asm("ex2.approx.f16x2 %0, %1;" : "=r"(r) : "r"(x)); return r;
}
__device__ __forceinline__ unsigned int hadd2(unsigned int a, unsigned int b) {
    unsigned int r; asm("add.rn.f16x2 %0, %1, %2;" : "=r"(r) : "r"(a), "r"(b)); return r;
}
__device__ __forceinline__ void h2_to_f32(unsigned int v, float& lo, float& hi) {
    asm("{\n\t"
        ".reg .b16 l, h;\n\t"
        "mov.b32 {l, h}, %2;\n\t"
        "cvt.f32.f16 %0, l;\n\t"
        "cvt.f32.f16 %1, h;\n\t"
        "}" : "=f"(lo), "=f"(hi) : "r"(v));
}

// grid = (M/64, B), 64 threads. Fused staging + fp16x2-MUFU mainloop.
// t = am2 + qx*xx + qy*xy + sn  (log2 units, t <= 0 always -> exp2 in [0,1],
// safe in fp16: no overflow; underflow floor 2^-24 is negligible mass).
__global__ __launch_bounds__(64)
void kde_main_kernel(const float* __restrict__ inputs,
                     const float* __restrict__ pts,
                     float* __restrict__ out,
                     int N, int M, float gamma2, float scale_out) {
    const int b = blockIdx.y;
    const int m = blockIdx.x * 64 + threadIdx.x;

    __shared__ __align__(16) float sxx[2048];
    __shared__ __align__(16) float sxy[2048];
    __shared__ __align__(16) float ssn[2048];

    // Stage + preprocess all N samples: (N,2) -> pair-packed SoA
    {
        const float4* src = (const float4*)(inputs + (size_t)b * N * 2);
        u64* dxx = (u64*)sxx;
        u64* dxy = (u64*)sxy;
        u64* dsn = (u64*)ssn;
        const int nv = N >> 1;               // float4s, 2 samples each
        for (int j = threadIdx.x; j < nv; j += 64) {
            float4 v = src[j];
            float s0 = -gamma2 * fmaf(v.x, v.x, v.y * v.y);
            float s1 = -gamma2 * fmaf(v.z, v.z, v.w * v.w);
            dxx[j] = pk2(v.x, v.z);
            dxy[j] = pk2(v.y, v.w);
            dsn[j] = pk2(s0, s1);
        }
    }

    // Point constants (log2 units)
    const float px = pts[2 * m], py = pts[2 * m + 1];
    const float qxs = 2.0f * gamma2 * px;
    const float qys = 2.0f * gamma2 * py;
    const float am2s = -gamma2 * fmaf(px, px, py * py);

    __syncthreads();

    const u64 qx2  = pk2(qxs, qxs);
    const u64 qy2  = pk2(qys, qys);
    const u64 am22 = pk2(am2s, am2s);

    const ulonglong2* hx = (const ulonglong2*)sxx;
    const ulonglong2* hy = (const ulonglong2*)sxy;
    const ulonglong2* hs = (const ulonglong2*)ssn;

    float acc0 = 0.0f, acc1 = 0.0f;

    const int nq = N >> 3;                   // 8 samples (4 pairs) per iter
    #pragma unroll 4
    for (int q = 0; q < nq; q++) {
        int j = 2 * q;
        ulonglong2 X0 = hx[j], X1 = hx[j + 1];
        ulonglong2 Y0 = hy[j], Y1 = hy[j + 1];
        ulonglong2 S0 = hs[j], S1 = hs[j + 1];

        // fp32 dots, am2 folded in so t <= 0 (fp16-safe range)
        u64 ta = fma2(qx2, X0.x, S0.x); ta = fma2(qy2, Y0.x, ta); ta = add2(ta, am22);
        u64 tb = fma2(qx2, X0.y, S0.y); tb = fma2(qy2, Y0.y, tb); tb = add2(tb, am22);
        u64 tc = fma2(qx2, X1.x, S1.x); tc = fma2(qy2, Y1.x, tc); tc = add2(tc, am22);
        u64 td = fma2(qx2, X1.y, S1.y); td = fma2(qy2, Y1.y, td); td = add2(td, am22);

        // fp16x2 exp2: 4 MUFU instrs for 8 exponentials
        unsigned int ea = hex2(f16x2_of(ta));
        unsigned int eb = hex2(f16x2_of(tb));
        unsigned int ec = hex2(f16x2_of(tc));
        unsigned int ed = hex2(f16x2_of(td));

        // fp16 pairwise tree (values <= 1 each, partial <= 4), flush to fp32
        unsigned int u = hadd2(ea, eb);
        unsigned int v = hadd2(ec, ed);
        unsigned int w = hadd2(u, v);
        float lo, hi;
        h2_to_f32(w, lo, hi);
        acc0 += lo;
        acc1 += hi;
    }

    out[(size_t)b * M + m] = (acc0 + acc1) * scale_out;
}

extern "C" void kernel_launch(void* const* d_in, const int* in_sizes, int n_in,
                              void* d_out, int out_size) {
    const float* inputs = (const float*)d_in[0];   // (B, N, 2) float32
    const float* pts    = (const float*)d_in[1];   // (M, 2) float32
    float* out          = (float*)d_out;           // (B, M) float32

    const int d = 2;
    const int M  = in_sizes[1] / d;                // 512
    const int BN = in_sizes[0] / d;                // B*N
    const int B  = out_size / M;                   // 128
    const int N  = BN / B;                         // 2048

    // Silverman bandwidth (d=2)
    double h = pow(4.0 / (d + 2), 1.0 / (d + 4)) * pow((double)N, -1.0 / (d + 4));
    double coef = 1.0 / pow(2.0 * M_PI * h * h, d / 2.0);
    double gamma = 0.5 / (h * h);
    float gamma2 = (float)(gamma * 1.4426950408889634);  // fold 1/ln2 for ex2
    float scale_out = (float)(coef / (double)N);

    dim3 grid(M / 64, B);   // (8, 128) = 1024 blocks, 64 threads
    kde_main_kernel<<<grid, 64>>>(inputs, pts, out, N, M, gamma2, scale_out);
}

// round 13
// speedup vs baseline: 1.3607x; 1.1475x over previous
#include <cuda_runtime.h>
#include <math.h>

typedef unsigned long long u64;

__device__ __forceinline__ void upk2(u64 v, float& lo, float& hi) {
    asm("mov.b64 {%0, %1}, %2;" : "=f"(lo), "=f"(hi) : "l"(v));
}
__device__ __forceinline__ u64 pk2(float lo, float hi) {
    u64 r; asm("mov.b64 %0, {%1, %2};" : "=l"(r) : "f"(lo), "f"(hi)); return r;
}
__device__ __forceinline__ u64 fma2(u64 a, u64 b, u64 c) {
    u64 d; asm("fma.rn.f32x2 %0, %1, %2, %3;" : "=l"(d) : "l"(a), "l"(b), "l"(c)); return d;
}
__device__ __forceinline__ u64 add2(u64 a, u64 b) {
    u64 d; asm("add.rn.f32x2 %0, %1, %2;" : "=l"(d) : "l"(a), "l"(b)); return d;
}
// pack a fp32 pair (as u64) into f16x2 with round-to-nearest
__device__ __forceinline__ unsigned int f16x2_of(u64 t) {
    float lo, hi; upk2(t, lo, hi);
    unsigned int r;
    asm("cvt.rn.f16x2.f32 %0, %1, %2;" : "=r"(r) : "f"(hi), "f"(lo));
    return r;
}
// packed fp16 exp2: ONE MUFU instruction, TWO exponentials
__device__ __forceinline__ unsigned int hex2(unsigned int x) {
    unsigned int r; asm("ex2.approx.f16x2 %0, %1;" : "=r"(r) : "r"(x)); return r;
}
__device__ __forceinline__ unsigned int hadd2(unsigned int a, unsigned int b) {
    unsigned int r; asm("add.rn.f16x2 %0, %1, %2;" : "=r"(r) : "r"(a), "r"(b)); return r;
}
__device__ __forceinline__ void h2_to_f32(unsigned int v, float& lo, float& hi) {
    asm("{\n\t"
        ".reg .b16 l, h;\n\t"
        "mov.b32 {l, h}, %2;\n\t"
        "cvt.f32.f16 %0, l;\n\t"
        "cvt.f32.f16 %1, h;\n\t"
        "}" : "=f"(lo), "=f"(hi) : "r"(v));
}

// grid = (M/64, B), 128 threads. In-block split-K: threads t and t+64 share
// one m; each covers half of N. fp32 dots -> fp16x2 MUFU exp2 -> fp16 tree.
// t = am2 + qx*xx + qy*xy + sn <= 0 always -> exp2(t) in [0,1], fp16-safe.
__global__ __launch_bounds__(128)
void kde_main_kernel(const float* __restrict__ inputs,
                     const float* __restrict__ pts,
                     float* __restrict__ out,
                     int N, int M, float gamma2, float scale_out) {
    const int b = blockIdx.y;
    const int lane = threadIdx.x & 63;
    const int half = threadIdx.x >> 6;           // 0 or 1
    const int m = blockIdx.x * 64 + lane;
    const int Nc = N >> 1;                       // samples per thread

    __shared__ __align__(16) float sxx[2048];
    __shared__ __align__(16) float sxy[2048];
    __shared__ __align__(16) float ssn[2048];
    __shared__ float spart[64];

    // Stage + preprocess all N samples: (N,2) -> pair-packed SoA
    {
        const float4* src = (const float4*)(inputs + (size_t)b * N * 2);
        u64* dxx = (u64*)sxx;
        u64* dxy = (u64*)sxy;
        u64* dsn = (u64*)ssn;
        const int nv = N >> 1;                   // float4s, 2 samples each
        for (int j = threadIdx.x; j < nv; j += 128) {
            float4 v = src[j];
            float s0 = -gamma2 * fmaf(v.x, v.x, v.y * v.y);
            float s1 = -gamma2 * fmaf(v.z, v.z, v.w * v.w);
            dxx[j] = pk2(v.x, v.z);
            dxy[j] = pk2(v.y, v.w);
            dsn[j] = pk2(s0, s1);
        }
    }

    // Point constants (log2 units)
    const float px = pts[2 * m], py = pts[2 * m + 1];
    const float qxs = 2.0f * gamma2 * px;
    const float qys = 2.0f * gamma2 * py;
    const float am2s = -gamma2 * fmaf(px, px, py * py);

    __syncthreads();

    const u64 qx2  = pk2(qxs, qxs);
    const u64 qy2  = pk2(qys, qys);
    const u64 am22 = pk2(am2s, am2s);

    // This thread's half: samples [half*Nc, (half+1)*Nc)
    const int base = half * (Nc >> 2);           // ulonglong2 index offset
    const ulonglong2* hx = (const ulonglong2*)sxx + base;
    const ulonglong2* hy = (const ulonglong2*)sxy + base;
    const ulonglong2* hs = (const ulonglong2*)ssn + base;

    float acc0 = 0.0f, acc1 = 0.0f;

    const int nq = Nc >> 3;                      // 8 samples (4 pairs) / iter
    #pragma unroll 4
    for (int q = 0; q < nq; q++) {
        int j = 2 * q;
        ulonglong2 X0 = hx[j], X1 = hx[j + 1];
        ulonglong2 Y0 = hy[j], Y1 = hy[j + 1];
        ulonglong2 S0 = hs[j], S1 = hs[j + 1];

        // fp32 dots, am2 folded in so t <= 0 (fp16-safe range)
        u64 ta = fma2(qx2, X0.x, S0.x); ta = fma2(qy2, Y0.x, ta); ta = add2(ta, am22);
        u64 tb = fma2(qx2, X0.y, S0.y); tb = fma2(qy2, Y0.y, tb); tb = add2(tb, am22);
        u64 tc = fma2(qx2, X1.x, S1.x); tc = fma2(qy2, Y1.x, tc); tc = add2(tc, am22);
        u64 td = fma2(qx2, X1.y, S1.y); td = fma2(qy2, Y1.y, td); td = add2(td, am22);

        // fp16x2 exp2: 4 MUFU instrs for 8 exponentials
        unsigned int ea = hex2(f16x2_of(ta));
        unsigned int eb = hex2(f16x2_of(tb));
        unsigned int ec = hex2(f16x2_of(tc));
        unsigned int ed = hex2(f16x2_of(td));

        // fp16 pairwise tree (each value <= 1, partial <= 4), flush to fp32
        unsigned int u = hadd2(ea, eb);
        unsigned int v = hadd2(ec, ed);
        unsigned int w = hadd2(u, v);
        float lo, hi;
        h2_to_f32(w, lo, hi);
        acc0 += lo;
        acc1 += hi;
    }

    float total = (acc0 + acc1) * scale_out;

    // Combine the two halves (fixed order: half0 + half1 -> deterministic).
    if (half == 1) spart[lane] = total;
    __syncthreads();
    if (half == 0) {
        out[(size_t)b * M + m] = total + spart[lane];
    }
}

extern "C" void kernel_launch(void* const* d_in, const int* in_sizes, int n_in,
                              void* d_out, int out_size) {
    const float* inputs = (const float*)d_in[0];   // (B, N, 2) float32
    const float* pts    = (const float*)d_in[1];   // (M, 2) float32
    float* out          = (float*)d_out;           // (B, M) float32

    const int d = 2;
    const int M  = in_sizes[1] / d;                // 512
    const int BN = in_sizes[0] / d;                // B*N
    const int B  = out_size / M;                   // 128
    const int N  = BN / B;                         // 2048

    // Silverman bandwidth (d=2)
    double h = pow(4.0 / (d + 2), 1.0 / (d + 4)) * pow((double)N, -1.0 / (d + 4));
    double coef = 1.0 / pow(2.0 * M_PI * h * h, d / 2.0);
    double gamma = 0.5 / (h * h);
    float gamma2 = (float)(gamma * 1.4426950408889634);  // fold 1/ln2 for ex2
    float scale_out = (float)(coef / (double)N);

    dim3 grid(M / 64, B);   // (8, 128) = 1024 blocks, 128 threads
    kde_main_kernel<<<grid, 128>>>(inputs, pts, out, N, M, gamma2, scale_out);
}

// round 14
// speedup vs baseline: 1.3621x; 1.0010x over previous
#include <cuda_runtime.h>
#include <math.h>

typedef unsigned long long u64;

__device__ __forceinline__ void upk2(u64 v, float& lo, float& hi) {
    asm("mov.b64 {%0, %1}, %2;" : "=f"(lo), "=f"(hi) : "l"(v));
}
__device__ __forceinline__ u64 pk2(float lo, float hi) {
    u64 r; asm("mov.b64 %0, {%1, %2};" : "=l"(r) : "f"(lo), "f"(hi)); return r;
}
__device__ __forceinline__ u64 fma2(u64 a, u64 b, u64 c) {
    u64 d; asm("fma.rn.f32x2 %0, %1, %2, %3;" : "=l"(d) : "l"(a), "l"(b), "l"(c)); return d;
}
__device__ __forceinline__ u64 add2(u64 a, u64 b) {
    u64 d; asm("add.rn.f32x2 %0, %1, %2;" : "=l"(d) : "l"(a), "l"(b)); return d;
}
__device__ __forceinline__ unsigned int f16x2_of(u64 t) {
    float lo, hi; upk2(t, lo, hi);
    unsigned int r;
    asm("cvt.rn.f16x2.f32 %0, %1, %2;" : "=r"(r) : "f"(hi), "f"(lo));
    return r;
}
__device__ __forceinline__ unsigned int hex2(unsigned int x) {
    unsigned int r; asm("ex2.approx.f16x2 %0, %1;" : "=r"(r) : "r"(x)); return r;
}
__device__ __forceinline__ unsigned int hadd2(unsigned int a, unsigned int b) {
    unsigned int r; asm("add.rn.f16x2 %0, %1, %2;" : "=r"(r) : "r"(a), "r"(b)); return r;
}
__device__ __forceinline__ void h2_to_f32(unsigned int v, float& lo, float& hi) {
    asm("{\n\t"
        ".reg .b16 l, h;\n\t"
        "mov.b32 {l, h}, %2;\n\t"
        "cvt.f32.f16 %0, l;\n\t"
        "cvt.f32.f16 %1, h;\n\t"
        "}" : "=f"(lo), "=f"(hi) : "r"(v));
}

// One point-chain over 4 sample-pairs: fp32 dot (am2 folded, t<=0) ->
// fp16x2 MUFU exp2 -> fp16 pairwise tree -> fp32 accumulate.
__device__ __forceinline__ void eval8(
    const ulonglong2& X0, const ulonglong2& X1,
    const ulonglong2& Y0, const ulonglong2& Y1,
    const ulonglong2& S0, const ulonglong2& S1,
    u64 qx2, u64 qy2, u64 am22, float& acc0, float& acc1)
{
    u64 ta = fma2(qx2, X0.x, S0.x); ta = fma2(qy2, Y0.x, ta); ta = add2(ta, am22);
    u64 tb = fma2(qx2, X0.y, S0.y); tb = fma2(qy2, Y0.y, tb); tb = add2(tb, am22);
    u64 tc = fma2(qx2, X1.x, S1.x); tc = fma2(qy2, Y1.x, tc); tc = add2(tc, am22);
    u64 td = fma2(qx2, X1.y, S1.y); td = fma2(qy2, Y1.y, td); td = add2(td, am22);

    unsigned int ea = hex2(f16x2_of(ta));
    unsigned int eb = hex2(f16x2_of(tb));
    unsigned int ec = hex2(f16x2_of(tc));
    unsigned int ed = hex2(f16x2_of(td));

    unsigned int u = hadd2(ea, eb);
    unsigned int v = hadd2(ec, ed);
    unsigned int w = hadd2(u, v);
    float lo, hi;
    h2_to_f32(w, lo, hi);
    acc0 += lo;
    acc1 += hi;
}

// grid = (M/64, B), 128 threads = 4 K-quarters x 32 lanes.
// Each lane owns TWO points (m0 = bx*64+lane, m1 = m0+32); each quarter
// covers N/4 samples. Quarter partials combined via smem (fixed order).
__global__ __launch_bounds__(128)
void kde_main_kernel(const float* __restrict__ inputs,
                     const float* __restrict__ pts,
                     float* __restrict__ out,
                     int N, int M, float gamma2, float scale_out) {
    const int b = blockIdx.y;
    const int lane = threadIdx.x & 31;
    const int quad = threadIdx.x >> 5;           // 0..3
    const int m0 = blockIdx.x * 64 + lane;
    const int m1 = m0 + 32;
    const int Nc = N >> 2;                       // samples per quarter

    __shared__ __align__(16) float sxx[2048];
    __shared__ __align__(16) float sxy[2048];
    __shared__ __align__(16) float ssn[2048];
    __shared__ float spart[3][64];

    // Stage + preprocess all N samples: (N,2) -> pair-packed SoA
    {
        const float4* src = (const float4*)(inputs + (size_t)b * N * 2);
        u64* dxx = (u64*)sxx;
        u64* dxy = (u64*)sxy;
        u64* dsn = (u64*)ssn;
        const int nv = N >> 1;                   // float4s, 2 samples each
        for (int j = threadIdx.x; j < nv; j += 128) {
            float4 v = src[j];
            float s0 = -gamma2 * fmaf(v.x, v.x, v.y * v.y);
            float s1 = -gamma2 * fmaf(v.z, v.z, v.w * v.w);
            dxx[j] = pk2(v.x, v.z);
            dxy[j] = pk2(v.y, v.w);
            dsn[j] = pk2(s0, s1);
        }
    }

    // Point constants for both owned points (log2 units)
    const float pxA = pts[2 * m0], pyA = pts[2 * m0 + 1];
    const float pxB = pts[2 * m1], pyB = pts[2 * m1 + 1];
    const float qxA = 2.0f * gamma2 * pxA, qyA = 2.0f * gamma2 * pyA;
    const float qxB = 2.0f * gamma2 * pxB, qyB = 2.0f * gamma2 * pyB;
    const float amA = -gamma2 * fmaf(pxA, pxA, pyA * pyA);
    const float amB = -gamma2 * fmaf(pxB, pxB, pyB * pyB);

    __syncthreads();

    const u64 qxA2 = pk2(qxA, qxA), qyA2 = pk2(qyA, qyA), amA2 = pk2(amA, amA);
    const u64 qxB2 = pk2(qxB, qxB), qyB2 = pk2(qyB, qyB), amB2 = pk2(amB, amB);

    // This quarter's chunk: samples [quad*Nc, (quad+1)*Nc)
    const int base = quad * (Nc >> 2);           // ulonglong2 index offset
    const ulonglong2* hx = (const ulonglong2*)sxx + base;
    const ulonglong2* hy = (const ulonglong2*)sxy + base;
    const ulonglong2* hs = (const ulonglong2*)ssn + base;

    float a0 = 0.f, a1 = 0.f, b0 = 0.f, b1 = 0.f;

    const int nq = Nc >> 3;                      // 8 samples per iter
    #pragma unroll 2
    for (int q = 0; q < nq; q++) {
        int j = 2 * q;
        ulonglong2 X0 = hx[j], X1 = hx[j + 1];
        ulonglong2 Y0 = hy[j], Y1 = hy[j + 1];
        ulonglong2 S0 = hs[j], S1 = hs[j + 1];

        eval8(X0, X1, Y0, Y1, S0, S1, qxA2, qyA2, amA2, a0, a1);  // point m0
        eval8(X0, X1, Y0, Y1, S0, S1, qxB2, qyB2, amB2, b0, b1);  // point m1
    }

    float totA = (a0 + a1) * scale_out;
    float totB = (b0 + b1) * scale_out;

    // Combine quarters: quads 1-3 publish, quad 0 reduces in fixed order.
    if (quad != 0) {
        spart[quad - 1][lane]      = totA;
        spart[quad - 1][lane + 32] = totB;
    }
    __syncthreads();
    if (quad == 0) {
        float sA = totA + spart[0][lane]      + spart[1][lane]      + spart[2][lane];
        float sB = totB + spart[0][lane + 32] + spart[1][lane + 32] + spart[2][lane + 32];
        const size_t bm = (size_t)b * M;
        out[bm + m0] = sA;
        out[bm + m1] = sB;
    }
}

extern "C" void kernel_launch(void* const* d_in, const int* in_sizes, int n_in,
                              void* d_out, int out_size) {
    const float* inputs = (const float*)d_in[0];   // (B, N, 2) float32
    const float* pts    = (const float*)d_in[1];   // (M, 2) float32
    float* out          = (float*)d_out;           // (B, M) float32

    const int d = 2;
    const int M  = in_sizes[1] / d;                // 512
    const int BN = in_sizes[0] / d;                // B*N
    const int B  = out_size / M;                   // 128
    const int N  = BN / B;                         // 2048

    // Silverman bandwidth (d=2)
    double h = pow(4.0 / (d + 2), 1.0 / (d + 4)) * pow((double)N, -1.0 / (d + 4));
    double coef = 1.0 / pow(2.0 * M_PI * h * h, d / 2.0);
    double gamma = 0.5 / (h * h);
    float gamma2 = (float)(gamma * 1.4426950408889634);  // fold 1/ln2 for ex2
    float scale_out = (float)(coef / (double)N);

    dim3 grid(M / 64, B);   // (8, 128) = 1024 blocks, 128 threads
    kde_main_kernel<<<grid, 128>>>(inputs, pts, out, N, M, gamma2, scale_out);
}

// round 15
// speedup vs baseline: 1.4450x; 1.0609x over previous
#include <cuda_runtime.h>
#include <math.h>

typedef unsigned long long u64;

__device__ __forceinline__ void upk2(u64 v, float& lo, float& hi) {
    asm("mov.b64 {%0, %1}, %2;" : "=f"(lo), "=f"(hi) : "l"(v));
}
__device__ __forceinline__ u64 pk2(float lo, float hi) {
    u64 r; asm("mov.b64 %0, {%1, %2};" : "=l"(r) : "f"(lo), "f"(hi)); return r;
}
__device__ __forceinline__ u64 fma2(u64 a, u64 b, u64 c) {
    u64 d; asm("fma.rn.f32x2 %0, %1, %2, %3;" : "=l"(d) : "l"(a), "l"(b), "l"(c)); return d;
}
__device__ __forceinline__ u64 add2(u64 a, u64 b) {
    u64 d; asm("add.rn.f32x2 %0, %1, %2;" : "=l"(d) : "l"(a), "l"(b)); return d;
}
__device__ __forceinline__ unsigned int f16x2_of(u64 t) {
    float lo, hi; upk2(t, lo, hi);
    unsigned int r;
    asm("cvt.rn.f16x2.f32 %0, %1, %2;" : "=r"(r) : "f"(hi), "f"(lo));
    return r;
}
__device__ __forceinline__ unsigned int hex2(unsigned int x) {
    unsigned int r; asm("ex2.approx.f16x2 %0, %1;" : "=r"(r) : "r"(x)); return r;
}
__device__ __forceinline__ unsigned int hadd2(unsigned int a, unsigned int b) {
    unsigned int r; asm("add.rn.f16x2 %0, %1, %2;" : "=r"(r) : "r"(a), "r"(b)); return r;
}
__device__ __forceinline__ void h2_to_f32(unsigned int v, float& lo, float& hi) {
    asm("{\n\t"
        ".reg .b16 l, h;\n\t"
        "mov.b32 {l, h}, %2;\n\t"
        "cvt.f32.f16 %0, l;\n\t"
        "cvt.f32.f16 %1, h;\n\t"
        "}" : "=f"(lo), "=f"(hi) : "r"(v));
}

// Stage 1: fp32 dots (am2 folded, t <= 0) + cvt to fp16x2. Returns the 4
// converted pair-arguments for one point over 8 samples.
__device__ __forceinline__ uint4 dots8(
    const ulonglong2& X0, const ulonglong2& X1,
    const ulonglong2& Y0, const ulonglong2& Y1,
    const ulonglong2& S0, const ulonglong2& S1,
    u64 qx2, u64 qy2, u64 am22)
{
    u64 ta = fma2(qx2, X0.x, S0.x); ta = fma2(qy2, Y0.x, ta); ta = add2(ta, am22);
    u64 tb = fma2(qx2, X0.y, S0.y); tb = fma2(qy2, Y0.y, tb); tb = add2(tb, am22);
    u64 tc = fma2(qx2, X1.x, S1.x); tc = fma2(qy2, Y1.x, tc); tc = add2(tc, am22);
    u64 td = fma2(qx2, X1.y, S1.y); td = fma2(qy2, Y1.y, td); td = add2(td, am22);
    uint4 r;
    r.x = f16x2_of(ta);
    r.y = f16x2_of(tb);
    r.z = f16x2_of(tc);
    r.w = f16x2_of(td);
    return r;
}

// Stage 2: fp16x2 MUFU exp2 + fp16 pairwise tree + fp32 accumulate.
__device__ __forceinline__ void exp8_acc(uint4 c, float& acc0, float& acc1) {
    unsigned int ea = hex2(c.x);
    unsigned int eb = hex2(c.y);
    unsigned int ec = hex2(c.z);
    unsigned int ed = hex2(c.w);
    unsigned int u = hadd2(ea, eb);
    unsigned int v = hadd2(ec, ed);
    unsigned int w = hadd2(u, v);
    float lo, hi;
    h2_to_f32(w, lo, hi);
    acc0 += lo;
    acc1 += hi;
}

// grid = (M/64, B), 128 threads = 4 K-quarters x 32 lanes.
// Each lane owns TWO points (m0, m1 = m0+32); each quarter covers N/4
// samples. Software-pipelined: exp-stage of iter q runs on carried regs
// while dot-stage of iter q+1 issues (overlapping MUFU/cvt with FMA chains).
__global__ __launch_bounds__(128)
void kde_main_kernel(const float* __restrict__ inputs,
                     const float* __restrict__ pts,
                     float* __restrict__ out,
                     int N, int M, float gamma2, float scale_out) {
    const int b = blockIdx.y;
    const int lane = threadIdx.x & 31;
    const int quad = threadIdx.x >> 5;           // 0..3
    const int m0 = blockIdx.x * 64 + lane;
    const int m1 = m0 + 32;
    const int Nc = N >> 2;                       // samples per quarter

    __shared__ __align__(16) float sxx[2048];
    __shared__ __align__(16) float sxy[2048];
    __shared__ __align__(16) float ssn[2048];
    __shared__ float spart[3][64];

    // Stage + preprocess all N samples: (N,2) -> pair-packed SoA
    {
        const float4* src = (const float4*)(inputs + (size_t)b * N * 2);
        u64* dxx = (u64*)sxx;
        u64* dxy = (u64*)sxy;
        u64* dsn = (u64*)ssn;
        const int nv = N >> 1;                   // float4s, 2 samples each
        for (int j = threadIdx.x; j < nv; j += 128) {
            float4 v = src[j];
            float s0 = -gamma2 * fmaf(v.x, v.x, v.y * v.y);
            float s1 = -gamma2 * fmaf(v.z, v.z, v.w * v.w);
            dxx[j] = pk2(v.x, v.z);
            dxy[j] = pk2(v.y, v.w);
            dsn[j] = pk2(s0, s1);
        }
    }

    // Point constants for both owned points (log2 units)
    const float pxA = pts[2 * m0], pyA = pts[2 * m0 + 1];
    const float pxB = pts[2 * m1], pyB = pts[2 * m1 + 1];
    const float qxA = 2.0f * gamma2 * pxA, qyA = 2.0f * gamma2 * pyA;
    const float qxB = 2.0f * gamma2 * pxB, qyB = 2.0f * gamma2 * pyB;
    const float amA = -gamma2 * fmaf(pxA, pxA, pyA * pyA);
    const float amB = -gamma2 * fmaf(pxB, pxB, pyB * pyB);

    __syncthreads();

    const u64 qxA2 = pk2(qxA, qxA), qyA2 = pk2(qyA, qyA), amA2 = pk2(amA, amA);
    const u64 qxB2 = pk2(qxB, qxB), qyB2 = pk2(qyB, qyB), amB2 = pk2(amB, amB);

    // This quarter's chunk: samples [quad*Nc, (quad+1)*Nc)
    const int base = quad * (Nc >> 2);           // ulonglong2 index offset
    const ulonglong2* hx = (const ulonglong2*)sxx + base;
    const ulonglong2* hy = (const ulonglong2*)sxy + base;
    const ulonglong2* hs = (const ulonglong2*)ssn + base;

    float a0 = 0.f, a1 = 0.f, b0 = 0.f, b1 = 0.f;

    const int nq = Nc >> 3;                      // 8 samples per iter

    // Pipeline prologue: dots+cvt for iter 0 into carried registers.
    uint4 cA, cB;
    {
        ulonglong2 X0 = hx[0], X1 = hx[1];
        ulonglong2 Y0 = hy[0], Y1 = hy[1];
        ulonglong2 S0 = hs[0], S1 = hs[1];
        cA = dots8(X0, X1, Y0, Y1, S0, S1, qxA2, qyA2, amA2);
        cB = dots8(X0, X1, Y0, Y1, S0, S1, qxB2, qyB2, amB2);
    }

    #pragma unroll 2
    for (int q = 1; q < nq; q++) {
        int j = 2 * q;
        ulonglong2 X0 = hx[j], X1 = hx[j + 1];
        ulonglong2 Y0 = hy[j], Y1 = hy[j + 1];
        ulonglong2 S0 = hs[j], S1 = hs[j + 1];

        // exp-stage for the PREVIOUS iter (independent of the loads above)
        exp8_acc(cA, a0, a1);
        exp8_acc(cB, b0, b1);

        // dot-stage for THIS iter -> carried registers
        cA = dots8(X0, X1, Y0, Y1, S0, S1, qxA2, qyA2, amA2);
        cB = dots8(X0, X1, Y0, Y1, S0, S1, qxB2, qyB2, amB2);
    }

    // Pipeline epilogue
    exp8_acc(cA, a0, a1);
    exp8_acc(cB, b0, b1);

    float totA = (a0 + a1) * scale_out;
    float totB = (b0 + b1) * scale_out;

    // Combine quarters: quads 1-3 publish, quad 0 reduces in fixed order.
    if (quad != 0) {
        spart[quad - 1][lane]      = totA;
        spart[quad - 1][lane + 32] = totB;
    }
    __syncthreads();
    if (quad == 0) {
        float sA = totA + spart[0][lane]      + spart[1][lane]      + spart[2][lane];
        float sB = totB + spart[0][lane + 32] + spart[1][lane + 32] + spart[2][lane + 32];
        const size_t bm = (size_t)b * M;
        out[bm + m0] = sA;
        out[bm + m1] = sB;
    }
}

extern "C" void kernel_launch(void* const* d_in, const int* in_sizes, int n_in,
                              void* d_out, int out_size) {
    const float* inputs = (const float*)d_in[0];   // (B, N, 2) float32
    const float* pts    = (const float*)d_in[1];   // (M, 2) float32
    float* out          = (float*)d_out;           // (B, M) float32

    const int d = 2;
    const int M  = in_sizes[1] / d;                // 512
    const int BN = in_sizes[0] / d;                // B*N
    const int B  = out_size / M;                   // 128
    const int N  = BN / B;                         // 2048

    // Silverman bandwidth (d=2)
    double h = pow(4.0 / (d + 2), 1.0 / (d + 4)) * pow((double)N, -1.0 / (d + 4));
    double coef = 1.0 / pow(2.0 * M_PI * h * h, d / 2.0);
    double gamma = 0.5 / (h * h);
    float gamma2 = (float)(gamma * 1.4426950408889634);  // fold 1/ln2 for ex2
    float scale_out = (float)(coef / (double)N);

    dim3 grid(M / 64, B);   // (8, 128) = 1024 blocks, 128 threads
    kde_main_kernel<<<grid, 128>>>(inputs, pts, out, N, M, gamma2, scale_out);
}